// round 1
// baseline (speedup 1.0000x reference)
#include <cuda_runtime.h>
#include <math.h>

#define B_DIM 128
#define S_DIM 512
#define IN_DIM 128
#define D_DIM 64
#define G_DIM 256   // 4*D
#define TILE_R 64

// Scratch (sanctioned __device__ globals; no runtime allocation)
__device__ float g_xs[(size_t)S_DIM * B_DIM * G_DIM];   // [s][b][4D]
__device__ float g_Wc[IN_DIM * G_DIM];                  // W_in @ W_s
__device__ float g_bc[G_DIM];                           // b_in @ W_s + b_s

// ---------------------------------------------------------------------------
// Kernel 1: fold input projection into the sLSTM input weights.
// W_comb[d][j] = sum_e W_in[d][e] * W_s[e][j];  b_comb[j] = b_s[j] + sum_e b_in[e]*W_s[e][j]
// ---------------------------------------------------------------------------
__global__ void combine_weights(const float* __restrict__ W_in,
                                const float* __restrict__ b_in,
                                const float* __restrict__ W_s,
                                const float* __restrict__ b_s) {
    int j = threadIdx.x;           // 0..255
    int d = blockIdx.x;            // 0..128 (128 = bias block)
    if (d < IN_DIM) {
        float acc = 0.f;
#pragma unroll
        for (int e = 0; e < D_DIM; e++)
            acc += W_in[d * D_DIM + e] * W_s[e * G_DIM + j];
        g_Wc[d * G_DIM + j] = acc;
    } else {
        float acc = b_s[j];
#pragma unroll
        for (int e = 0; e < D_DIM; e++)
            acc += b_in[e] * W_s[e * G_DIM + j];
        g_bc[j] = acc;
    }
}

// ---------------------------------------------------------------------------
// Kernel 2: xs[s][b][j] = sum_d x[b][s][d] * W_comb[d][j] + b_comb[j]
// GEMM M=65536, N=256, K=128.  Weight column lives in registers (reused for
// 64 rows); x tile broadcast from SMEM via float4.
// ---------------------------------------------------------------------------
__global__ __launch_bounds__(256) void xs_gemm(const float* __restrict__ x) {
    __shared__ __align__(16) float xsm[TILE_R][IN_DIM];
    int t = threadIdx.x;
    int row0 = blockIdx.x * TILE_R;

    // Load 64 rows of x (coalesced float4)
    const float4* xg = reinterpret_cast<const float4*>(x + (size_t)row0 * IN_DIM);
    float4* xs4 = reinterpret_cast<float4*>(&xsm[0][0]);
#pragma unroll
    for (int i = 0; i < (TILE_R * IN_DIM / 4) / 256; i++)
        xs4[t + i * 256] = xg[t + i * 256];

    // Weight column t in registers
    float w[IN_DIM];
#pragma unroll
    for (int d = 0; d < IN_DIM; d++) w[d] = g_Wc[d * G_DIM + t];
    float bc = g_bc[t];
    __syncthreads();

    for (int r = 0; r < TILE_R; r += 4) {
        float a0 = bc, a1 = bc, a2 = bc, a3 = bc;
        const float4* p0 = reinterpret_cast<const float4*>(xsm[r + 0]);
        const float4* p1 = reinterpret_cast<const float4*>(xsm[r + 1]);
        const float4* p2 = reinterpret_cast<const float4*>(xsm[r + 2]);
        const float4* p3 = reinterpret_cast<const float4*>(xsm[r + 3]);
#pragma unroll
        for (int dq = 0; dq < IN_DIM / 4; dq++) {
            float4 v0 = p0[dq];
            a0 += v0.x * w[4*dq] + v0.y * w[4*dq+1] + v0.z * w[4*dq+2] + v0.w * w[4*dq+3];
            float4 v1 = p1[dq];
            a1 += v1.x * w[4*dq] + v1.y * w[4*dq+1] + v1.z * w[4*dq+2] + v1.w * w[4*dq+3];
            float4 v2 = p2[dq];
            a2 += v2.x * w[4*dq] + v2.y * w[4*dq+1] + v2.z * w[4*dq+2] + v2.w * w[4*dq+3];
            float4 v3 = p3[dq];
            a3 += v3.x * w[4*dq] + v3.y * w[4*dq+1] + v3.z * w[4*dq+2] + v3.w * w[4*dq+3];
        }
#pragma unroll
        for (int rr = 0; rr < 4; rr++) {
            int row = row0 + r + rr;
            int bb = row >> 9;     // /S_DIM (512)
            int ss = row & 511;
            float av = (rr == 0) ? a0 : (rr == 1) ? a1 : (rr == 2) ? a2 : a3;
            g_xs[((size_t)ss * B_DIM + bb) * G_DIM + t] = av;
        }
    }
}

// ---------------------------------------------------------------------------
// Kernel 3: persistent recurrence. 1 CTA per batch element, 256 threads.
// Per-step loop computes only what the carry needs (g, state, LN, k, v, im,
// fm, C_m, n_m). q/om/num/den/gate/h_f computed once after the loop.
// ---------------------------------------------------------------------------
__global__ __launch_bounds__(256) void recur(
    const float* __restrict__ R_s,
    const float* __restrict__ ln_g, const float* __restrict__ ln_b,
    const float* __restrict__ Wq, const float* __restrict__ Wk,
    const float* __restrict__ Wv,
    const float* __restrict__ wi, const float* __restrict__ bi_p,
    const float* __restrict__ wf, const float* __restrict__ bf_p,
    const float* __restrict__ Wo, const float* __restrict__ bo,
    const float* __restrict__ W_fuse, const float* __restrict__ b_fuse,
    float* __restrict__ out)
{
    __shared__ __align__(16) float hs[64], cs[64], ns[64], nm[64];
    __shared__ __align__(16) float hso[64], ksm[64], vsm[64];
    __shared__ __align__(16) float gact[256];
    __shared__ __align__(16) float wi_s[64], wf_s[64], lng_s[64], lnb_s[64];
    __shared__ __align__(16) float qsm[64], omsm[64], numsm[64], hmsm[64];
    __shared__ float red[8];
    __shared__ float red2[2];
    __shared__ float gpart[4][64];

    int t = threadIdx.x;
    int b = blockIdx.x;
    int lane = t & 31;

    // --- register-resident weights ---
    float R[64];
#pragma unroll
    for (int d = 0; d < 64; d++) R[d] = R_s[d * 256 + t];

    float Wkv[64];
    if (t < 128) {
        const float* Wsel = (t < 64) ? Wk : Wv;
        int c = t & 63;
#pragma unroll
        for (int d = 0; d < 64; d++) Wkv[d] = Wsel[d * 64 + c];
    }

    if (t < 64) {
        hs[t] = 0.f; cs[t] = 0.f; ns[t] = 1.f; nm[t] = 0.f;
        wi_s[t] = wi[t]; wf_s[t] = wf[t];
        lng_s[t] = ln_g[t]; lnb_s[t] = ln_b[t];
    }
    float bi = bi_p[0];
    float bf = bf_p[0];

    float Creg[16];
#pragma unroll
    for (int i = 0; i < 16; i++) Creg[i] = 0.f;

    __syncthreads();

    const float* xsp = g_xs + (size_t)b * G_DIM + t;
    float gnext = xsp[0];

    const int ci = t >> 2;           // C_m row owned (4 threads per row)
    const int jb = (t & 3) << 4;     // 16-column slice

    for (int s = 0; s < S_DIM; s++) {
        // ---- Phase A: g = xs_t + h_s @ R_s ; activation ----
        float gv = gnext;
        {
            int sn = (s + 1 < S_DIM) ? (s + 1) : s;
            gnext = xsp[(size_t)sn * (B_DIM * G_DIM)];   // prefetch next step
        }
        const float4* h4 = reinterpret_cast<const float4*>(hs);
#pragma unroll
        for (int dq = 0; dq < 16; dq++) {
            float4 h = h4[dq];
            gv += h.x * R[4*dq]   + h.y * R[4*dq+1]
                + h.z * R[4*dq+2] + h.w * R[4*dq+3];
        }
        float a;
        if (t < 64)       a = tanhf(gv);
        else if (t < 128) a = expf(gv);
        else              a = 1.f / (1.f + expf(-gv));
        gact[t] = a;
        __syncthreads();                                   // s1

        // ---- Phase B: sLSTM state + LN stats (threads 0..63) ----
        if (t < 64) {
            float z = gact[t], ig = gact[64 + t], f = gact[128 + t], o = gact[192 + t];
            float c = f * cs[t] + ig * z;
            float n = f * ns[t] + ig;
            cs[t] = c; ns[t] = n;
            float h = o * c / n;
            hs[t] = h;
            float s1v = h, s2v = h * h;
#pragma unroll
            for (int off = 16; off > 0; off >>= 1) {
                s1v += __shfl_xor_sync(0xffffffffu, s1v, off);
                s2v += __shfl_xor_sync(0xffffffffu, s2v, off);
            }
            if (lane == 0) { red[(t >> 5) * 2] = s1v; red[(t >> 5) * 2 + 1] = s2v; }
        }
        __syncthreads();                                   // s2

        if (t < 64) {
            float mu  = (red[0] + red[2]) * 0.015625f;
            float ms  = (red[1] + red[3]) * 0.015625f;
            float inv = rsqrtf(ms - mu * mu + 1e-5f);
            float ho  = (hs[t] - mu) * inv * lng_s[t] + lnb_s[t];
            hso[t] = ho;
            float pi = ho * wi_s[t], pf = ho * wf_s[t];
#pragma unroll
            for (int off = 16; off > 0; off >>= 1) {
                pi += __shfl_xor_sync(0xffffffffu, pi, off);
                pf += __shfl_xor_sync(0xffffffffu, pf, off);
            }
            if (lane == 0) { red[4 + (t >> 5)] = pi; red[6 + (t >> 5)] = pf; }
        }
        __syncthreads();                                   // s3

        float im = expf(red[4] + red[5] + bi);
        float fm = 1.f / (1.f + expf(-(red[6] + red[7] + bf)));

        // ---- Phase C: k = hso@Wk * d^-1/2 ; v = hso@Wv (threads 0..127) ----
        if (t < 128) {
            float acc = 0.f;
            const float4* ho4 = reinterpret_cast<const float4*>(hso);
#pragma unroll
            for (int dq = 0; dq < 16; dq++) {
                float4 h = ho4[dq];
                acc += h.x * Wkv[4*dq]   + h.y * Wkv[4*dq+1]
                     + h.z * Wkv[4*dq+2] + h.w * Wkv[4*dq+3];
            }
            if (t < 64) ksm[t] = acc * 0.125f;   // 1/sqrt(64)
            else        vsm[t - 64] = acc;
        }
        __syncthreads();                                   // s4

        // ---- Phase D: C_m rank-1 update (all threads), n_m update ----
        {
            float imv = im * vsm[ci];
            const float4* k4 = reinterpret_cast<const float4*>(ksm + jb);
#pragma unroll
            for (int q4 = 0; q4 < 4; q4++) {
                float4 kq = k4[q4];
                Creg[q4*4+0] = fm * Creg[q4*4+0] + imv * kq.x;
                Creg[q4*4+1] = fm * Creg[q4*4+1] + imv * kq.y;
                Creg[q4*4+2] = fm * Creg[q4*4+2] + imv * kq.z;
                Creg[q4*4+3] = fm * Creg[q4*4+3] + imv * kq.w;
            }
            if (t < 64) nm[t] = fm * nm[t] + im * ksm[t];
        }
        // no barrier needed: next-iter writers are all fenced by s1..s4
    }

    // ---- Final-step epilogue: q, om, num, den, h_m, fusion gate ----
    __syncthreads();
    if (t < 128) {
        int c = t & 63;
        const float* W = (t < 64) ? Wq : Wo;
        float acc = (t < 64) ? 0.f : bo[c];
#pragma unroll
        for (int d = 0; d < 64; d++) acc += hso[d] * W[d * 64 + c];
        if (t < 64) qsm[c] = acc;
        else        omsm[c] = 1.f / (1.f + expf(-acc));
    }
    __syncthreads();
    {
        float np = 0.f;
        const float4* q4p = reinterpret_cast<const float4*>(qsm + jb);
#pragma unroll
        for (int q4 = 0; q4 < 4; q4++) {
            float4 qq = q4p[q4];
            np += Creg[q4*4+0] * qq.x + Creg[q4*4+1] * qq.y
                + Creg[q4*4+2] * qq.z + Creg[q4*4+3] * qq.w;
        }
        np += __shfl_xor_sync(0xffffffffu, np, 1);
        np += __shfl_xor_sync(0xffffffffu, np, 2);
        if ((t & 3) == 0) numsm[ci] = np;
    }
    if (t < 64) {
        float dp = nm[t] * qsm[t];
#pragma unroll
        for (int off = 16; off > 0; off >>= 1)
            dp += __shfl_xor_sync(0xffffffffu, dp, off);
        if (lane == 0) red2[t >> 5] = dp;
    }
    __syncthreads();
    if (t < 64) {
        float den = fmaxf(fabsf(red2[0] + red2[1]), 1.f);
        hmsm[t] = omsm[t] * numsm[t] / den;
    }
    __syncthreads();
    {
        int j = t & 63, rb2 = (t >> 6) * 32;
        float gp = 0.f;
#pragma unroll
        for (int r = 0; r < 32; r++) {
            int rr = rb2 + r;
            float catv = (rr < 64) ? hso[rr] : hmsm[rr - 64];
            gp += catv * W_fuse[rr * 64 + j];
        }
        gpart[t >> 6][j] = gp;
    }
    __syncthreads();
    if (t < 64) {
        float gs = gpart[0][t] + gpart[1][t] + gpart[2][t] + gpart[3][t] + b_fuse[t];
        float gate = 1.f / (1.f + expf(-gs));
        out[b * 64 + t] = gate * hmsm[t] + (1.f - gate) * hso[t];
    }
}

// ---------------------------------------------------------------------------
extern "C" void kernel_launch(void* const* d_in, const int* in_sizes, int n_in,
                              void* d_out, int out_size) {
    const float* x      = (const float*)d_in[0];
    const float* W_in   = (const float*)d_in[1];
    const float* b_in   = (const float*)d_in[2];
    const float* W_s    = (const float*)d_in[3];
    const float* R_s    = (const float*)d_in[4];
    const float* b_s    = (const float*)d_in[5];
    const float* ln_g   = (const float*)d_in[6];
    const float* ln_b   = (const float*)d_in[7];
    const float* Wq     = (const float*)d_in[8];
    const float* Wk     = (const float*)d_in[9];
    const float* Wv     = (const float*)d_in[10];
    const float* wi     = (const float*)d_in[11];
    const float* bi     = (const float*)d_in[12];
    const float* wf     = (const float*)d_in[13];
    const float* bf     = (const float*)d_in[14];
    const float* Wo     = (const float*)d_in[15];
    const float* bo     = (const float*)d_in[16];
    const float* W_fuse = (const float*)d_in[17];
    const float* b_fuse = (const float*)d_in[18];
    float* out = (float*)d_out;

    combine_weights<<<IN_DIM + 1, G_DIM>>>(W_in, b_in, W_s, b_s);
    xs_gemm<<<(B_DIM * S_DIM) / TILE_R, 256>>>(x);
    recur<<<B_DIM, 256>>>(R_s, ln_g, ln_b, Wq, Wk, Wv, wi, bi, wf, bf,
                          Wo, bo, W_fuse, b_fuse, out);
}

// round 3
// speedup vs baseline: 1.6009x; 1.6009x over previous
#include <cuda_runtime.h>
#include <math.h>

#define B_DIM 128
#define S_DIM 512
#define IN_DIM 128
#define D_DIM 64
#define G_DIM 256   // 4*D
#define TILE_R 64

typedef unsigned long long ull;

// ---- packed f32x2 helpers (Blackwell; ptxas never auto-fuses these) ----
__device__ __forceinline__ void ffma2(ull& a, ull x, ull y) {
    asm("fma.rn.f32x2 %0, %1, %2, %0;" : "+l"(a) : "l"(x), "l"(y));
}
__device__ __forceinline__ ull fmaf2(ull a, ull b, ull c) {
    ull d; asm("fma.rn.f32x2 %0, %1, %2, %3;" : "=l"(d) : "l"(a), "l"(b), "l"(c)); return d;
}
__device__ __forceinline__ ull mulf2(ull x, ull y) {
    ull r; asm("mul.rn.f32x2 %0, %1, %2;" : "=l"(r) : "l"(x), "l"(y)); return r;
}
__device__ __forceinline__ ull addf2(ull x, ull y) {
    ull r; asm("add.rn.f32x2 %0, %1, %2;" : "=l"(r) : "l"(x), "l"(y)); return r;
}
__device__ __forceinline__ ull packf2(float lo, float hi) {
    ull r; asm("mov.b64 %0, {%1, %2};" : "=l"(r) : "f"(lo), "f"(hi)); return r;
}
__device__ __forceinline__ float2 unpackf2(ull v) {
    float2 f; asm("mov.b64 {%0, %1}, %2;" : "=f"(f.x), "=f"(f.y) : "l"(v)); return f;
}

// Scratch (sanctioned __device__ globals)
__device__ float g_xs[(size_t)S_DIM * B_DIM * G_DIM];   // [s][b][4D]
__device__ float g_Wc[IN_DIM * G_DIM];                  // W_in @ W_s
__device__ float g_bc[G_DIM];                           // b_in @ W_s + b_s

// ---------------------------------------------------------------------------
// Kernel 1: fold input projection into sLSTM input weights.
// ---------------------------------------------------------------------------
__global__ void combine_weights(const float* __restrict__ W_in,
                                const float* __restrict__ b_in,
                                const float* __restrict__ W_s,
                                const float* __restrict__ b_s) {
    int j = threadIdx.x;
    int d = blockIdx.x;
    if (d < IN_DIM) {
        float acc = 0.f;
#pragma unroll
        for (int e = 0; e < D_DIM; e++)
            acc += W_in[d * D_DIM + e] * W_s[e * G_DIM + j];
        g_Wc[d * G_DIM + j] = acc;
    } else {
        float acc = b_s[j];
#pragma unroll
        for (int e = 0; e < D_DIM; e++)
            acc += b_in[e] * W_s[e * G_DIM + j];
        g_bc[j] = acc;
    }
}

// ---------------------------------------------------------------------------
// Kernel 2: xs[s][b][j] = x[b][s][:] @ W_comb[:,j] + b_comb[j]  (packed f32x2)
// Each ulonglong2 = 4 floats; a 128-float row = 32 ulonglong2 -> dq in [0,32).
// ---------------------------------------------------------------------------
__global__ __launch_bounds__(256) void xs_gemm(const float* __restrict__ x) {
    __shared__ __align__(16) float xsm[TILE_R][IN_DIM];
    int t = threadIdx.x;
    int row0 = blockIdx.x * TILE_R;

    const float4* xg = reinterpret_cast<const float4*>(x + (size_t)row0 * IN_DIM);
    float4* xs4 = reinterpret_cast<float4*>(&xsm[0][0]);
#pragma unroll
    for (int i = 0; i < (TILE_R * IN_DIM / 4) / 256; i++)
        xs4[t + i * 256] = xg[t + i * 256];

    // Weight column t packed into 64 f32x2 regs (pair p covers d=2p,2p+1)
    ull w2[64];
#pragma unroll
    for (int i = 0; i < 64; i++)
        w2[i] = packf2(g_Wc[(2 * i) * G_DIM + t], g_Wc[(2 * i + 1) * G_DIM + t]);
    float bc = g_bc[t];
    __syncthreads();

    for (int r = 0; r < TILE_R; r += 4) {
        ull a0 = 0, a1 = 0, a2 = 0, a3 = 0;
        const ulonglong2* p0 = reinterpret_cast<const ulonglong2*>(xsm[r + 0]);
        const ulonglong2* p1 = reinterpret_cast<const ulonglong2*>(xsm[r + 1]);
        const ulonglong2* p2 = reinterpret_cast<const ulonglong2*>(xsm[r + 2]);
        const ulonglong2* p3 = reinterpret_cast<const ulonglong2*>(xsm[r + 3]);
#pragma unroll
        for (int dq = 0; dq < 32; dq++) {   // FIX: 32 iterations covers full K=128
            ulonglong2 v0 = p0[dq]; ffma2(a0, v0.x, w2[2*dq]); ffma2(a0, v0.y, w2[2*dq+1]);
            ulonglong2 v1 = p1[dq]; ffma2(a1, v1.x, w2[2*dq]); ffma2(a1, v1.y, w2[2*dq+1]);
            ulonglong2 v2 = p2[dq]; ffma2(a2, v2.x, w2[2*dq]); ffma2(a2, v2.y, w2[2*dq+1]);
            ulonglong2 v3 = p3[dq]; ffma2(a3, v3.x, w2[2*dq]); ffma2(a3, v3.y, w2[2*dq+1]);
        }
#pragma unroll
        for (int rr = 0; rr < 4; rr++) {
            ull av = (rr == 0) ? a0 : (rr == 1) ? a1 : (rr == 2) ? a2 : a3;
            float2 f = unpackf2(av);
            int row = row0 + r + rr;
            int bb = row >> 9;
            int ss = row & 511;
            g_xs[((size_t)ss * B_DIM + bb) * G_DIM + t] = f.x + f.y + bc;
        }
    }
}

// ---------------------------------------------------------------------------
// Kernel 3: persistent recurrence, 1 CTA/batch, 256 threads, 3 barriers/step.
// ---------------------------------------------------------------------------
__global__ __launch_bounds__(256) void recur(
    const float* __restrict__ R_s,
    const float* __restrict__ ln_g, const float* __restrict__ ln_b,
    const float* __restrict__ Wq, const float* __restrict__ Wk,
    const float* __restrict__ Wv,
    const float* __restrict__ wi, const float* __restrict__ bi_p,
    const float* __restrict__ wf, const float* __restrict__ bf_p,
    const float* __restrict__ Wo, const float* __restrict__ bo,
    const float* __restrict__ W_fuse, const float* __restrict__ b_fuse,
    float* __restrict__ out)
{
    __shared__ __align__(16) float hs[64], hso[64], ksm[64], vsm[64], nm[64];
    __shared__ __align__(16) float gact[256];
    __shared__ float scl[2];                          // im, fm
    __shared__ __align__(16) float qsm[64], omsm[64], numsm[64], hmsm[64];
    __shared__ float red2[2];
    __shared__ float gpart[4][64];

    int t = threadIdx.x;
    int b = blockIdx.x;
    int lane = t & 31;

    // recurrent weight column t, packed (pair i covers rows 2i,2i+1 of 64)
    ull R2[32];
#pragma unroll
    for (int i = 0; i < 32; i++)
        R2[i] = packf2(R_s[(2 * i) * G_DIM + t], R_s[(2 * i + 1) * G_DIM + t]);

    ull W2[32];
    if (t < 128) {
        const float* Wsel = (t < 64) ? Wk : Wv;
        int c = t & 63;
#pragma unroll
        for (int i = 0; i < 32; i++)
            W2[i] = packf2(Wsel[(2 * i) * 64 + c], Wsel[(2 * i + 1) * 64 + c]);
    }

    // warp-0 per-lane LN / gate constants (lane handles dims d0=lane, d1=lane+32)
    float cs0 = 0.f, cs1 = 0.f, ns0 = 1.f, ns1 = 1.f;
    float g0 = 0.f, g1 = 0.f, lb0 = 0.f, lb1 = 0.f;
    float gwi0 = 0.f, gwi1 = 0.f, gwf0 = 0.f, gwf1 = 0.f;
    float Sgwi = 0.f, Sgwf = 0.f, Sbwi = 0.f, Sbwf = 0.f;
    if (t < 32) {
        int d0 = t, d1 = t + 32;
        g0 = ln_g[d0]; g1 = ln_g[d1]; lb0 = ln_b[d0]; lb1 = ln_b[d1];
        float wi0 = wi[d0], wi1 = wi[d1], wf0 = wf[d0], wf1 = wf[d1];
        gwi0 = g0 * wi0; gwi1 = g1 * wi1; gwf0 = g0 * wf0; gwf1 = g1 * wf1;
        float sa = gwi0 + gwi1, sb = gwf0 + gwf1;
        float sc = lb0 * wi0 + lb1 * wi1, sd = lb0 * wf0 + lb1 * wf1;
#pragma unroll
        for (int off = 16; off > 0; off >>= 1) {
            sa += __shfl_xor_sync(0xffffffffu, sa, off);
            sb += __shfl_xor_sync(0xffffffffu, sb, off);
            sc += __shfl_xor_sync(0xffffffffu, sc, off);
            sd += __shfl_xor_sync(0xffffffffu, sd, off);
        }
        Sgwi = sa; Sgwf = sb; Sbwi = sc; Sbwf = sd;
    }
    if (t < 64) { hs[t] = 0.f; nm[t] = 0.f; }
    float bi = bi_p[0];
    float bf = bf_p[0];

    ull C2[8];
#pragma unroll
    for (int i = 0; i < 8; i++) C2[i] = 0ull;

    __syncthreads();

    const float* xsp = g_xs + (size_t)b * G_DIM + t;
    float gnext = xsp[0];

    const int ci = t >> 2;           // C_m row owned (4 threads per row)
    const int jb = (t & 3) << 4;     // 16-column slice

    for (int s = 0; s < S_DIM; s++) {
        // ---- Phase A: g = xs_t + h_s @ R_s ; activation ----
        float gv = gnext;
        {
            int sn = (s + 1 < S_DIM) ? (s + 1) : s;
            gnext = xsp[(size_t)sn * (B_DIM * G_DIM)];
        }
        {
            ull a0 = 0, a1 = 0, a2 = 0, a3 = 0;
            const ulonglong2* h2 = reinterpret_cast<const ulonglong2*>(hs);
#pragma unroll
            for (int q = 0; q < 8; q++) {
                ulonglong2 u = h2[2 * q];
                ulonglong2 w = h2[2 * q + 1];
                ffma2(a0, u.x, R2[4 * q]);
                ffma2(a1, u.y, R2[4 * q + 1]);
                ffma2(a2, w.x, R2[4 * q + 2]);
                ffma2(a3, w.y, R2[4 * q + 3]);
            }
            a0 = addf2(a0, a1); a2 = addf2(a2, a3); a0 = addf2(a0, a2);
            float2 p = unpackf2(a0);
            gv += p.x + p.y;
        }
        float act;
        if (t < 64) {                       // tanh
            float e = __expf(2.f * gv);
            act = 1.f - __fdividef(2.f, e + 1.f);
        } else if (t < 128) {               // exp
            act = __expf(gv);
        } else {                            // sigmoid
            float e = __expf(-gv);
            act = __fdividef(1.f, 1.f + e);
        }
        gact[t] = act;
        __syncthreads();                                   // s1

        // ---- Phase B (warp 0): state, LN, im/fm — one fused reduction ----
        if (t < 32) {
            int d0 = t, d1 = t + 32;
            float z0 = gact[d0], i0 = gact[64 + d0], f0 = gact[128 + d0], o0 = gact[192 + d0];
            float z1 = gact[d1], i1 = gact[64 + d1], f1 = gact[128 + d1], o1 = gact[192 + d1];
            cs0 = f0 * cs0 + i0 * z0; ns0 = f0 * ns0 + i0;
            cs1 = f1 * cs1 + i1 * z1; ns1 = f1 * ns1 + i1;
            float h0 = __fdividef(o0 * cs0, ns0);
            float h1 = __fdividef(o1 * cs1, ns1);
            hs[d0] = h0; hs[d1] = h1;
            float r1 = h0 + h1;
            float r2 = h0 * h0 + h1 * h1;
            float r3 = h0 * gwi0 + h1 * gwi1;
            float r4 = h0 * gwf0 + h1 * gwf1;
#pragma unroll
            for (int off = 16; off > 0; off >>= 1) {
                r1 += __shfl_xor_sync(0xffffffffu, r1, off);
                r2 += __shfl_xor_sync(0xffffffffu, r2, off);
                r3 += __shfl_xor_sync(0xffffffffu, r3, off);
                r4 += __shfl_xor_sync(0xffffffffu, r4, off);
            }
            float mu = r1 * 0.015625f;
            float inv = rsqrtf(r2 * 0.015625f - mu * mu + 1e-5f);
            hso[d0] = (h0 - mu) * inv * g0 + lb0;
            hso[d1] = (h1 - mu) * inv * g1 + lb1;
            if (t == 0) {
                float pi = inv * (r3 - mu * Sgwi) + Sbwi + bi;
                float pf = inv * (r4 - mu * Sgwf) + Sbwf + bf;
                scl[0] = __expf(pi);
                float ef = __expf(-pf);
                scl[1] = __fdividef(1.f, 1.f + ef);
            }
        }
        __syncthreads();                                   // s2

        // ---- Phase C: k = hso@Wk * d^-1/2 ; v = hso@Wv (threads 0..127) ----
        if (t < 128) {
            ull a0 = 0, a1 = 0, a2 = 0, a3 = 0;
            const ulonglong2* h2 = reinterpret_cast<const ulonglong2*>(hso);
#pragma unroll
            for (int q = 0; q < 8; q++) {
                ulonglong2 u = h2[2 * q];
                ulonglong2 w = h2[2 * q + 1];
                ffma2(a0, u.x, W2[4 * q]);
                ffma2(a1, u.y, W2[4 * q + 1]);
                ffma2(a2, w.x, W2[4 * q + 2]);
                ffma2(a3, w.y, W2[4 * q + 3]);
            }
            a0 = addf2(a0, a1); a2 = addf2(a2, a3); a0 = addf2(a0, a2);
            float2 p = unpackf2(a0);
            float acc = p.x + p.y;
            if (t < 64) ksm[t] = acc * 0.125f;
            else        vsm[t - 64] = acc;
        }
        __syncthreads();                                   // s3

        // ---- Phase D: C_m rank-1 update, n_m update ----
        {
            float im = scl[0], fm = scl[1];
            float imv = im * vsm[ci];
            ull fm2 = packf2(fm, fm);
            ull iv2 = packf2(imv, imv);
            const ulonglong2* k2 = reinterpret_cast<const ulonglong2*>(ksm + jb);
#pragma unroll
            for (int q = 0; q < 4; q++) {
                ulonglong2 kv = k2[q];
                C2[2 * q]     = fmaf2(C2[2 * q],     fm2, mulf2(kv.x, iv2));
                C2[2 * q + 1] = fmaf2(C2[2 * q + 1], fm2, mulf2(kv.y, iv2));
            }
            if (t < 64) nm[t] = fm * nm[t] + im * ksm[t];
        }
        // no trailing barrier: next-iter hazards all fenced by s1..s3
    }

    // ---- Final-step epilogue: q, om, num, den, h_m, fusion gate ----
    float Creg[16];
#pragma unroll
    for (int i = 0; i < 8; i++) {
        float2 f = unpackf2(C2[i]);
        Creg[2 * i] = f.x; Creg[2 * i + 1] = f.y;
    }
    __syncthreads();
    if (t < 128) {
        int c = t & 63;
        const float* W = (t < 64) ? Wq : Wo;
        float acc = (t < 64) ? 0.f : bo[c];
#pragma unroll
        for (int d = 0; d < 64; d++) acc += hso[d] * W[d * 64 + c];
        if (t < 64) qsm[c] = acc;
        else        omsm[c] = 1.f / (1.f + expf(-acc));
    }
    __syncthreads();
    {
        float np = 0.f;
        const float4* q4p = reinterpret_cast<const float4*>(qsm + jb);
#pragma unroll
        for (int q4 = 0; q4 < 4; q4++) {
            float4 qq = q4p[q4];
            np += Creg[q4*4+0] * qq.x + Creg[q4*4+1] * qq.y
                + Creg[q4*4+2] * qq.z + Creg[q4*4+3] * qq.w;
        }
        np += __shfl_xor_sync(0xffffffffu, np, 1);
        np += __shfl_xor_sync(0xffffffffu, np, 2);
        if ((t & 3) == 0) numsm[ci] = np;
    }
    if (t < 64) {
        float dp = nm[t] * qsm[t];
#pragma unroll
        for (int off = 16; off > 0; off >>= 1)
            dp += __shfl_xor_sync(0xffffffffu, dp, off);
        if (lane == 0) red2[t >> 5] = dp;
    }
    __syncthreads();
    if (t < 64) {
        float den = fmaxf(fabsf(red2[0] + red2[1]), 1.f);
        hmsm[t] = omsm[t] * numsm[t] / den;
    }
    __syncthreads();
    {
        int j = t & 63, rb2 = (t >> 6) * 32;
        float gp = 0.f;
#pragma unroll
        for (int r = 0; r < 32; r++) {
            int rr = rb2 + r;
            float catv = (rr < 64) ? hso[rr] : hmsm[rr - 64];
            gp += catv * W_fuse[rr * 64 + j];
        }
        gpart[t >> 6][j] = gp;
    }
    __syncthreads();
    if (t < 64) {
        float gs = gpart[0][t] + gpart[1][t] + gpart[2][t] + gpart[3][t] + b_fuse[t];
        float gate = 1.f / (1.f + expf(-gs));
        out[b * 64 + t] = gate * hmsm[t] + (1.f - gate) * hso[t];
    }
}

// ---------------------------------------------------------------------------
extern "C" void kernel_launch(void* const* d_in, const int* in_sizes, int n_in,
                              void* d_out, int out_size) {
    const float* x      = (const float*)d_in[0];
    const float* W_in   = (const float*)d_in[1];
    const float* b_in   = (const float*)d_in[2];
    const float* W_s    = (const float*)d_in[3];
    const float* R_s    = (const float*)d_in[4];
    const float* b_s    = (const float*)d_in[5];
    const float* ln_g   = (const float*)d_in[6];
    const float* ln_b   = (const float*)d_in[7];
    const float* Wq     = (const float*)d_in[8];
    const float* Wk     = (const float*)d_in[9];
    const float* Wv     = (const float*)d_in[10];
    const float* wi     = (const float*)d_in[11];
    const float* bi     = (const float*)d_in[12];
    const float* wf     = (const float*)d_in[13];
    const float* bf     = (const float*)d_in[14];
    const float* Wo     = (const float*)d_in[15];
    const float* bo     = (const float*)d_in[16];
    const float* W_fuse = (const float*)d_in[17];
    const float* b_fuse = (const float*)d_in[18];
    float* out = (float*)d_out;

    combine_weights<<<IN_DIM + 1, G_DIM>>>(W_in, b_in, W_s, b_s);
    xs_gemm<<<(B_DIM * S_DIM) / TILE_R, 256>>>(x);
    recur<<<B_DIM, 256>>>(R_s, ln_g, ln_b, Wq, Wk, Wv, wi, bi, wf, bf,
                          Wo, bo, W_fuse, b_fuse, out);
}